// round 13
// baseline (speedup 1.0000x reference)
#include <cuda_runtime.h>
#include <cstdint>

// Problem constants
#define T_ALL   32
#define B_BINS  32
#define G_MAX   64

#define TB      8                    // t-values per CTA
#define TBLKS   (T_ALL / TB)         // 4
#define CHUNKS  37                   // 4*37 = 148 CTAs = 1/SM, co-resident
#define NBLOCKS (TBLKS * CHUNKS)     // 148
#define MAIN_THREADS 1024
#define SLICE   256                  // work-distribution granularity
#define NGROUPS (MAIN_THREADS / SLICE)   // 4 slice-groups per CTA

#define SM_CELLS (G_MAX * B_BINS * TB)      // 16384
#define SMEM_BYTES (SM_CELLS * 4)           // 64 KB

// z = 200*(lin_b - h) = b*D - H,  H = 200h + 220,  D = 440/31
// Window |z| < ZCUT = 4.0: width 8 < D => at most ONE transition bin.
#define DH_STEP  7.0967742f          // D/2
#define ZH_CUT   2.0f                // ZCUT/2
#define FB_MUL   14.0909091f         // 200*31/440
#define FB_ADD   15.7818182f         // (220+4.0)*31/440
#define MAGIC_F  12582912.0f         // 2^23 + 2^22
#define MAGIC_I  0x4B400000

// Per-CTA partial differentials (Q16.16 in u32, wrap-safe).
// Bin index stored bank-swizzled: cell(g,b) at offset g*32 + ((b+g)&31).
__device__ __align__(16) unsigned int g_part[NBLOCKS][SM_CELLS];  // 9.7 MB
__device__ unsigned int bar_a = 0;
__device__ unsigned int bar_b = 0;

static __device__ __forceinline__ float tanh_approx(float x) {
    float y;
    asm("tanh.approx.f32 %0, %1;" : "=f"(y) : "f"(x));
    return y;
}
static __device__ __forceinline__ int f2i_rn_magic(float x) {
    return __float_as_int(x + MAGIC_F) - MAGIC_I;
}

// Per-(item,t) differential update into smem accumulator [tt][g][swz(b)].
// Swizzle (b+g)&31 makes bank = (b+g) mod 32: edge warps (random g) spread
// across all banks instead of piling onto the ~10 hot b-banks.
static __device__ __forceinline__ void ect_update(
    unsigned int* accg, int g, int tt, float h, int sgn)
{
    // b_sat = clamp(ceil((H+ZCUT)/D), 0, 32) via magic round
    float fb = fmaf(h, FB_MUL, FB_ADD);
    fb = fminf(fmaxf(fb, -0.4f), 31.9f);
    const float tmag  = (fb + 0.5f) + MAGIC_F;
    const int   b_sat = __float_as_int(tmag) - MAGIC_I;   // [0,32]
    const float blof  = tmag - MAGIC_F;
    // z/2 at transition bin b_sat-1 (true h, not clamped)
    const float zh = fmaf(blof, DH_STEP, fmaf(h, -100.0f, -110.0f - DH_STEP));

    unsigned int* accp = accg + tt * (G_MAX * B_BINS);
    int q = 0;
    if (zh > -ZH_CUT && b_sat >= 1) {
        q = f2i_rn_magic(fmaf(tanh_approx(zh), 32768.0f, 32768.0f));
        atomicAdd(accp + ((b_sat - 1 + g) & 31), (unsigned int)(sgn * q));
    }
    if (b_sat < B_BINS)
        atomicAdd(accp + ((b_sat + g) & 31), (unsigned int)(sgn * (65536 - q)));
}

// ---------------------------------------------------------------------------
// Fused persistent kernel (R12 champion + graph-keyed bank swizzle).
// Phase 1: separate node/edge loops over 256-item interleaved slices;
//          plain integer smem atomics into [tt][g][swz(b)]; flush via STG.128.
// Grid barrier (148 co-resident CTAs). Phase 2: warp per (g,t): sum 37 chunk
// partials (unswizzling), warp-scan over b, emit.
// ---------------------------------------------------------------------------
__global__ void __launch_bounds__(MAIN_THREADS, 1)
ect_fused_kernel(const float* __restrict__ x, const float* __restrict__ v,
                 const int* __restrict__ ei, const int* __restrict__ batch,
                 int N, int E, float* __restrict__ out)
{
    extern __shared__ unsigned int s_acc[];

    const int tblk  = blockIdx.x / CHUNKS;
    const int chunk = blockIdx.x - tblk * CHUNKS;
    const int t0    = tblk * TB;
    const int tid   = threadIdx.x;
    const int gq    = tid >> 8;          // slice-group 0..3
    const int r     = tid & (SLICE - 1); // rank within slice

    {   // vectorized zero: 16384 u32 = 4096 uint4
        uint4* s4 = reinterpret_cast<uint4*>(s_acc);
        for (int i = tid; i < SM_CELLS / 4; i += MAIN_THREADS)
            s4[i] = make_uint4(0u, 0u, 0u, 0u);
    }

    float v0[TB], v1[TB], v2[TB];
#pragma unroll
    for (int tt = 0; tt < TB; ++tt) {
        v0[tt] = __ldg(&v[0 * T_ALL + t0 + tt]);
        v1[tt] = __ldg(&v[1 * T_ALL + t0 + tt]);
        v2[tt] = __ldg(&v[2 * T_ALL + t0 + tt]);
    }
    __syncthreads();

    // ---- Node loop: 256-item slices, interleaved (<=1 slice imbalance).
    for (int s = chunk + CHUNKS * gq; s * SLICE < N; s += CHUNKS * NGROUPS) {
        const int i = s * SLICE + r;
        if (i >= N) continue;
        const float a0 = __ldg(&x[3 * i]);
        const float a1 = __ldg(&x[3 * i + 1]);
        const float a2 = __ldg(&x[3 * i + 2]);
        const int   g  = __ldg(&batch[i]);
        unsigned int* accg = s_acc + g * B_BINS;
#pragma unroll
        for (int tt = 0; tt < TB; ++tt) {
            const float h = fmaf(a2, v2[tt], fmaf(a1, v1[tt], a0 * v0[tt]));
            ect_update(accg, g, tt, h, 1);
        }
    }

    // ---- Edge loop
    for (int s = chunk + CHUNKS * gq; s * SLICE < E; s += CHUNKS * NGROUPS) {
        const int e = s * SLICE + r;
        if (e >= E) continue;
        const int sn = __ldg(&ei[e]);
        const int dn = __ldg(&ei[E + e]);
        const float a0 = __ldg(&x[3 * sn]);
        const float a1 = __ldg(&x[3 * sn + 1]);
        const float a2 = __ldg(&x[3 * sn + 2]);
        const float c0 = __ldg(&x[3 * dn]);
        const float c1 = __ldg(&x[3 * dn + 1]);
        const float c2 = __ldg(&x[3 * dn + 2]);
        const int   g  = __ldg(&batch[sn]);
        unsigned int* accg = s_acc + g * B_BINS;
#pragma unroll
        for (int tt = 0; tt < TB; ++tt) {
            const float h1 = fmaf(a2, v2[tt], fmaf(a1, v1[tt], a0 * v0[tt]));
            const float h2 = fmaf(c2, v2[tt], fmaf(c1, v1[tt], c0 * v0[tt]));
            ect_update(accg, g, tt, fmaxf(h1, h2), -1);
        }
    }

    __syncthreads();

    // Flush: plain vectorized stores to this CTA's private slab.
    {
        uint4* dst = reinterpret_cast<uint4*>(g_part[blockIdx.x]);
        const uint4* s4 = reinterpret_cast<const uint4*>(s_acc);
        for (int i = tid; i < SM_CELLS / 4; i += MAIN_THREADS)
            dst[i] = s4[i];
    }
    __syncthreads();

    // ---- grid-wide barrier (148 co-resident CTAs) ----
    if (tid == 0) {
        unsigned int old;
        asm volatile("atom.add.release.gpu.u32 %0, [%1], %2;"
                     : "=r"(old) : "l"(&bar_a), "r"(1u) : "memory");
        unsigned int seen;
        do {
            asm volatile("ld.acquire.gpu.u32 %0, [%1];"
                         : "=r"(seen) : "l"(&bar_a) : "memory");
            if (seen >= (unsigned)NBLOCKS) break;
            __nanosleep(32);
        } while (true);
    }
    __syncthreads();

    // ---- Phase 2: warp per (g,t). lane = b (unswizzle on read).
    const int lane = tid & 31;
    const int gw   = blockIdx.x * (MAIN_THREADS / 32) + (tid >> 5);
    if (gw < G_MAX * T_ALL) {
        const int g     = gw >> 5;
        const int t     = gw & 31;
        const int ptblk = t / TB;
        const int ptt   = t % TB;
        const int off   = ptt * (G_MAX * B_BINS) + g * B_BINS
                        + ((lane + g) & 31);

        int s = 0;
#pragma unroll 8
        for (int c = 0; c < CHUNKS; ++c)
            s += (int)__ldcg(&g_part[ptblk * CHUNKS + c][off]);

#pragma unroll
        for (int o = 1; o < 32; o <<= 1) {
            const int nb = __shfl_up_sync(0xFFFFFFFFu, s, o);
            if (lane >= o) s += nb;
        }
        out[g * (B_BINS * T_ALL) + lane * T_ALL + t] = (float)s * (1.0f / 65536.0f);
    }

    // ---- reset barrier counters for graph replay ----
    __syncthreads();
    if (tid == 0) {
        const unsigned int old = atomicAdd(&bar_b, 1u);
        if (old == (unsigned)(NBLOCKS - 1)) {
            bar_a = 0u;
            bar_b = 0u;
        }
    }
}

// ---------------------------------------------------------------------------
extern "C" void kernel_launch(void* const* d_in, const int* in_sizes, int n_in,
                              void* d_out, int out_size)
{
    const float* x     = (const float*)d_in[0];
    const float* v     = (const float*)d_in[1];
    const int*   ei    = (const int*)d_in[3];
    const int*   batch = (const int*)d_in[4];

    const int N = in_sizes[4];
    const int E = in_sizes[3] / 2;

    cudaFuncSetAttribute(ect_fused_kernel,
                         cudaFuncAttributeMaxDynamicSharedMemorySize, SMEM_BYTES);

    ect_fused_kernel<<<NBLOCKS, MAIN_THREADS, SMEM_BYTES>>>(
        x, v, ei, batch, N, E, (float*)d_out);
}

// round 14
// speedup vs baseline: 1.0014x; 1.0014x over previous
#include <cuda_runtime.h>
#include <cstdint>

// Problem constants
#define T_ALL   32
#define B_BINS  32
#define G_MAX   64

#define TB      8                    // t-values per CTA
#define TBLKS   (T_ALL / TB)         // 4
#define CHUNKS  37                   // 4*37 = 148 CTAs = 1/SM, co-resident
#define NBLOCKS (TBLKS * CHUNKS)     // 148
#define MAIN_THREADS 1024
#define SLICE   256
#define NGROUPS (MAIN_THREADS / SLICE)   // 4 slice-groups per CTA

#define SM_CELLS (G_MAX * B_BINS * TB)      // 16384 logical cells
#define SMEM_BYTES (SM_CELLS * 8)           // 2 lane-parity copies = 128 KB

// z = 200*(lin_b - h) = b*D - H,  H = 200h + 220,  D = 440/31
// Window |z| < ZCUT = 4.0: width 8 < D => at most ONE transition bin.
#define DH_STEP  7.0967742f          // D/2
#define ZH_CUT   2.0f                // ZCUT/2
#define FB_MUL   14.0909091f         // 200*31/440
#define FB_ADD5  16.2818182f         // (220+4.0)*31/440 + 0.5  (ceil bias folded)
#define MAGIC_F  12582912.0f         // 2^23 + 2^22
#define MAGIC_I  0x4B400000

// Per-CTA partial differentials (Q16.16 in u32, wrap-safe).
// Slab layout [tt][g][swz(b)] (copies already merged at flush).
__device__ __align__(16) unsigned int g_part[NBLOCKS][SM_CELLS];  // 9.7 MB
__device__ unsigned int bar_a = 0;
__device__ unsigned int bar_b = 0;

static __device__ __forceinline__ float tanh_approx(float x) {
    float y;
    asm("tanh.approx.f32 %0, %1;" : "=f"(y) : "f"(x));
    return y;
}
static __device__ __forceinline__ int f2i_rn_magic(float x) {
    return __float_as_int(x + MAGIC_F) - MAGIC_I;
}

// Per-(item,t) differential update.
// SMEM cell (tt,g,b) -> u32 address 2*(tt*2048 + g*32 + ((b+g)&31)) + (lane&1).
// Lane-parity interleave: even lanes hit even banks, odd lanes odd banks
// (groups never collide) and same-address degree within a group is halved.
static __device__ __forceinline__ void ect_update(
    unsigned int* accg, int g, int tt, float h, int sgn)
{
    // b_sat = clamp(ceil((H+ZCUT)/D), 0, 32); ceil via magic round, +0.5 folded
    float fb = fmaf(h, FB_MUL, FB_ADD5);
    fb = fminf(fmaxf(fb, 0.1f), 32.4f);
    const float tmag  = fb + MAGIC_F;
    const int   b_sat = __float_as_int(tmag) - MAGIC_I;   // [0,32]
    const float blof  = tmag - MAGIC_F;                   // (float)b_sat
    // z/2 at transition bin b_sat-1 (true h, not clamped)
    const float zh = fmaf(blof, DH_STEP, fmaf(h, -100.0f, -110.0f - DH_STEP));

    unsigned int* accp = accg + tt * (2 * G_MAX * B_BINS);
    const int idx1 = (b_sat + g) & 31;          // swizzled saturation bin
    int q = 0;
    if (zh > -ZH_CUT && b_sat >= 1) {
        q = f2i_rn_magic(fmaf(tanh_approx(zh), 32768.0f, 32768.0f));
        atomicAdd(accp + 2 * ((idx1 - 1) & 31), (unsigned int)(sgn * q));
    }
    if (b_sat < B_BINS)
        atomicAdd(accp + 2 * idx1, (unsigned int)(sgn * (65536 - q)));
}

// ---------------------------------------------------------------------------
// Fused persistent kernel (R13 + lane-parity split accumulator).
// Phase 1: node/edge loops over 256-item interleaved slices; plain integer
//          smem atomics into the split accumulator; flush merges copies.
// Grid barrier (148 co-resident CTAs). Phase 2: warp per (g,t): sum 37 chunk
// partials (unswizzling), warp-scan over b, emit.
// ---------------------------------------------------------------------------
__global__ void __launch_bounds__(MAIN_THREADS, 1)
ect_fused_kernel(const float* __restrict__ x, const float* __restrict__ v,
                 const int* __restrict__ ei, const int* __restrict__ batch,
                 int N, int E, float* __restrict__ out)
{
    extern __shared__ unsigned int s_acc[];

    const int tblk  = blockIdx.x / CHUNKS;
    const int chunk = blockIdx.x - tblk * CHUNKS;
    const int t0    = tblk * TB;
    const int tid   = threadIdx.x;
    const int par   = tid & 1;           // lane parity -> accumulator copy
    const int gq    = tid >> 8;          // slice-group 0..3
    const int r     = tid & (SLICE - 1); // rank within slice

    {   // vectorized zero: 32768 u32 = 8192 uint4
        uint4* s4 = reinterpret_cast<uint4*>(s_acc);
        for (int i = tid; i < 2 * SM_CELLS / 4; i += MAIN_THREADS)
            s4[i] = make_uint4(0u, 0u, 0u, 0u);
    }

    float v0[TB], v1[TB], v2[TB];
#pragma unroll
    for (int tt = 0; tt < TB; ++tt) {
        v0[tt] = __ldg(&v[0 * T_ALL + t0 + tt]);
        v1[tt] = __ldg(&v[1 * T_ALL + t0 + tt]);
        v2[tt] = __ldg(&v[2 * T_ALL + t0 + tt]);
    }
    __syncthreads();

    // ---- Node loop: 256-item slices, interleaved (<=1 slice imbalance).
    for (int s = chunk + CHUNKS * gq; s * SLICE < N; s += CHUNKS * NGROUPS) {
        const int i = s * SLICE + r;
        if (i >= N) continue;
        const float a0 = __ldg(&x[3 * i]);
        const float a1 = __ldg(&x[3 * i + 1]);
        const float a2 = __ldg(&x[3 * i + 2]);
        const int   g  = __ldg(&batch[i]);
        unsigned int* accg = s_acc + 2 * (g * B_BINS) + par;
#pragma unroll
        for (int tt = 0; tt < TB; ++tt) {
            const float h = fmaf(a2, v2[tt], fmaf(a1, v1[tt], a0 * v0[tt]));
            ect_update(accg, g, tt, h, 1);
        }
    }

    // ---- Edge loop
    for (int s = chunk + CHUNKS * gq; s * SLICE < E; s += CHUNKS * NGROUPS) {
        const int e = s * SLICE + r;
        if (e >= E) continue;
        const int sn = __ldg(&ei[e]);
        const int dn = __ldg(&ei[E + e]);
        const float a0 = __ldg(&x[3 * sn]);
        const float a1 = __ldg(&x[3 * sn + 1]);
        const float a2 = __ldg(&x[3 * sn + 2]);
        const float c0 = __ldg(&x[3 * dn]);
        const float c1 = __ldg(&x[3 * dn + 1]);
        const float c2 = __ldg(&x[3 * dn + 2]);
        const int   g  = __ldg(&batch[sn]);
        unsigned int* accg = s_acc + 2 * (g * B_BINS) + par;
#pragma unroll
        for (int tt = 0; tt < TB; ++tt) {
            const float h1 = fmaf(a2, v2[tt], fmaf(a1, v1[tt], a0 * v0[tt]));
            const float h2 = fmaf(c2, v2[tt], fmaf(c1, v1[tt], c0 * v0[tt]));
            ect_update(accg, g, tt, fmaxf(h1, h2), -1);
        }
    }

    __syncthreads();

    // Flush: merge the two lane-parity copies, vectorized, into this CTA's slab.
    // uint4 j covers logical cells 2j (x,y) and 2j+1 (z,w).
    {
        uint2* dst = reinterpret_cast<uint2*>(g_part[blockIdx.x]);
        const uint4* s4 = reinterpret_cast<const uint4*>(s_acc);
        for (int i = tid; i < SM_CELLS / 2; i += MAIN_THREADS) {
            const uint4 a = s4[i];
            dst[i] = make_uint2(a.x + a.y, a.z + a.w);
        }
    }
    __syncthreads();

    // ---- grid-wide barrier (148 co-resident CTAs) ----
    if (tid == 0) {
        unsigned int old;
        asm volatile("atom.add.release.gpu.u32 %0, [%1], %2;"
                     : "=r"(old) : "l"(&bar_a), "r"(1u) : "memory");
        unsigned int seen;
        do {
            asm volatile("ld.acquire.gpu.u32 %0, [%1];"
                         : "=r"(seen) : "l"(&bar_a) : "memory");
            if (seen >= (unsigned)NBLOCKS) break;
            __nanosleep(32);
        } while (true);
    }
    __syncthreads();

    // ---- Phase 2: warp per (g,t). lane = b (unswizzle on read).
    const int lane = tid & 31;
    const int gw   = blockIdx.x * (MAIN_THREADS / 32) + (tid >> 5);
    if (gw < G_MAX * T_ALL) {
        const int g     = gw >> 5;
        const int t     = gw & 31;
        const int ptblk = t / TB;
        const int ptt   = t % TB;
        const int off   = ptt * (G_MAX * B_BINS) + g * B_BINS
                        + ((lane + g) & 31);

        int s = 0;
#pragma unroll 8
        for (int c = 0; c < CHUNKS; ++c)
            s += (int)__ldcg(&g_part[ptblk * CHUNKS + c][off]);

#pragma unroll
        for (int o = 1; o < 32; o <<= 1) {
            const int nb = __shfl_up_sync(0xFFFFFFFFu, s, o);
            if (lane >= o) s += nb;
        }
        out[g * (B_BINS * T_ALL) + lane * T_ALL + t] = (float)s * (1.0f / 65536.0f);
    }

    // ---- reset barrier counters for graph replay ----
    __syncthreads();
    if (tid == 0) {
        const unsigned int old = atomicAdd(&bar_b, 1u);
        if (old == (unsigned)(NBLOCKS - 1)) {
            bar_a = 0u;
            bar_b = 0u;
        }
    }
}

// ---------------------------------------------------------------------------
extern "C" void kernel_launch(void* const* d_in, const int* in_sizes, int n_in,
                              void* d_out, int out_size)
{
    const float* x     = (const float*)d_in[0];
    const float* v     = (const float*)d_in[1];
    const int*   ei    = (const int*)d_in[3];
    const int*   batch = (const int*)d_in[4];

    const int N = in_sizes[4];
    const int E = in_sizes[3] / 2;

    cudaFuncSetAttribute(ect_fused_kernel,
                         cudaFuncAttributeMaxDynamicSharedMemorySize, SMEM_BYTES);

    ect_fused_kernel<<<NBLOCKS, MAIN_THREADS, SMEM_BYTES>>>(
        x, v, ei, batch, N, E, (float*)d_out);
}